// round 9
// baseline (speedup 1.0000x reference)
#include <cuda_runtime.h>
#include <cuda_bf16.h>
#include <mma.h>

using namespace nvcuda;

// Problem constants
#define BB   256
#define TT   32
#define SS   2048
#define AA   64
#define PP   128
#define KFC  (SS + AA + PP)   // 2240
#define S4   (4 * SS)         // 8192

#define BKT  64
#define LDT  (BKT + 8)        // 72 bf16 smem stride

// ---------------------------------------------------------------------------
// Scratch (static device globals; no allocation anywhere)
// ---------------------------------------------------------------------------
__device__ __nv_bfloat16 g_fc1e[(long)SS * 2 * SS];    // fc1_eff packed [hi|lo]
__device__ __nv_bfloat16 g_fc2b[(long)SS * 2 * SS];
__device__ __nv_bfloat16 g_WWb [(long)S4 * 2 * SS];    // gate-interleaved rows: n' = 4s+g
__device__ __nv_bfloat16 g_fcWb[(long)SS * 2 * KFC];
__device__ __nv_bfloat16 g_hb  [(long)BB * 2 * SS];    // carry h, packed
__device__ __nv_bfloat16 g_x1b [(long)BB * 2 * SS];
__device__ __nv_bfloat16 g_x2b [(long)BB * 2 * SS];
__device__ __nv_bfloat16 g_hsb [(long)BB * 2 * KFC];   // cat[h, act, latent], packed
__device__ float         g_cell[(long)BB * SS];

// ---------------------------------------------------------------------------
// Helpers
// ---------------------------------------------------------------------------
__device__ __forceinline__ void split_write(__nv_bfloat16* hi_p, __nv_bfloat16* lo_p, float v) {
    __nv_bfloat16 h = __float2bfloat16(v);
    *hi_p = h;
    *lo_p = __float2bfloat16(v - __bfloat162float(h));
}

// One merged pack/init kernel: fc1_eff, fc2, WW (gate-interleaved), fcW, hs0,
// and rewards initialization (= rb).
__global__ void pack_all(const float* __restrict__ fc1W, const float* __restrict__ fc2W,
                         const float* __restrict__ WW,   const float* __restrict__ fcW,
                         const float* __restrict__ state, const float* __restrict__ acts,
                         const float* __restrict__ latent, const float* __restrict__ rb,
                         float* __restrict__ rewards,
                         __nv_bfloat16* __restrict__ fc1e, __nv_bfloat16* __restrict__ fc2b,
                         __nv_bfloat16* __restrict__ WWb,  __nv_bfloat16* __restrict__ fcWb,
                         __nv_bfloat16* __restrict__ hsb)
{
    const long N1 = (long)SS * SS;
    const long N2 = N1 + (long)SS * SS;
    const long N3 = N2 + (long)S4 * SS;
    const long N4 = N3 + (long)SS * KFC;
    const long N5 = N4 + (long)BB * KFC;
    const long N6 = N5 + (long)TT * BB;
    long idx = (long)blockIdx.x * 256 + threadIdx.x;
    if (idx < N1) {
        long n = idx / SS, k = idx % SS;
        float v = fc1W[n * 2 * SS + k] + fc1W[n * 2 * SS + SS + k];
        split_write(&fc1e[n * 2 * SS + k], &fc1e[n * 2 * SS + SS + k], v);
    } else if (idx < N2) {
        long j = idx - N1;
        long n = j / SS, k = j % SS;
        split_write(&fc2b[n * 2 * SS + k], &fc2b[n * 2 * SS + SS + k], fc2W[j]);
    } else if (idx < N3) {
        long j = idx - N2;
        long np = j / SS, k = j % SS;            // np = interleaved row
        long g = np & 3, s = np >> 2;            // src row = g*SS + s
        float v = WW[(g * SS + s) * SS + k];
        split_write(&WWb[np * 2 * SS + k], &WWb[np * 2 * SS + SS + k], v);
    } else if (idx < N4) {
        long j = idx - N3;
        long n = j / KFC, k = j % KFC;
        split_write(&fcWb[n * 2 * KFC + k], &fcWb[n * 2 * KFC + KFC + k], fcW[j]);
    } else if (idx < N5) {
        long j = idx - N4;
        int b = (int)(j / KFC), q = (int)(j % KFC);
        float v;
        if (q < SS)            v = state[(long)b * SS + q];
        else if (q < SS + AA)  v = acts[(long)b * (TT * AA) + (q - SS)];
        else                   v = latent[(long)b * PP + (q - SS - AA)];
        split_write(&hsb[(long)b * 2 * KFC + q], &hsb[(long)b * 2 * KFC + KFC + q], v);
    } else if (idx < N6) {
        rewards[idx - N5] = rb[0];
    }
}

// ---------------------------------------------------------------------------
// Split-bf16 GEMM (Ozaki 3-term):  C[256, N] = A[256,K] @ W[N,K]^T
// A, W packed [.,2K] bf16 [hi|lo]; per 64-K chunk: Ah*Wh + Ah*Wl + Al*Wh.
// EPI: 1 relu+split-bf16 store; 2 bias+relu+split-bf16; 3 = 2 + fp32 dual;
//      4 = fused LSTM gates epilogue (W gate-interleaved; relu(cc) then gates;
//          writes cell/preds/hsb/rewards; no C store).
// ---------------------------------------------------------------------------
#define CP16(s, g) asm volatile("cp.async.cg.shared.global [%0], [%1], 16;\n" :: "r"(s), "l"(g))

template<int BMp, int BNp, int WM, int WN, int THREADS, int STAGES, int EPI>
__global__ __launch_bounds__(THREADS, 1)
void gemm3(const __nv_bfloat16* __restrict__ Ab,
           const __nv_bfloat16* __restrict__ Wb,
           const float* __restrict__ bias,
           void* __restrict__ Cout,
           float* __restrict__ Cdual,
           int N, int K,
           float* __restrict__ cell,
           const float* __restrict__ rW,
           float* __restrict__ rewards,
           const float* __restrict__ acts,
           const float* __restrict__ latent,
           float* __restrict__ preds,
           __nv_bfloat16* __restrict__ hs,
           int t)
{
    extern __shared__ __align__(16) __nv_bfloat16 smem[];
    constexpr int TA = BMp * LDT;
    constexpr int TW = BNp * LDT;
    constexpr int STG = 2 * TA + 2 * TW;   // elements per stage

    const int tid = threadIdx.x;
    const int m0 = blockIdx.y * BMp;
    const int n0 = blockIdx.x * BNp;
    const int lda = 2 * K;
    const int nchunks = K / BKT;

    auto load_stage = [&](int buf, int c) {
        const int kb = c * BKT;
        __nv_bfloat16* sAhi = smem + buf * STG;
        __nv_bfloat16* sAlo = sAhi + TA;
        __nv_bfloat16* sWhi = sAlo + TA;
        __nv_bfloat16* sWlo = sWhi + TW;
#pragma unroll
        for (int i = 0; i < BMp * 8 / THREADS; ++i) {
            int f = tid + i * THREADS;
            int r = f >> 3, cb = (f & 7) * 8;
            const __nv_bfloat16* g = Ab + (long)(m0 + r) * lda + kb + cb;
            CP16((unsigned)__cvta_generic_to_shared(sAhi + r * LDT + cb), g);
            CP16((unsigned)__cvta_generic_to_shared(sAlo + r * LDT + cb), g + K);
        }
#pragma unroll
        for (int i = 0; i < BNp * 8 / THREADS; ++i) {
            int f = tid + i * THREADS;
            int r = f >> 3, cb = (f & 7) * 8;
            const __nv_bfloat16* g = Wb + (long)(n0 + r) * lda + kb + cb;
            CP16((unsigned)__cvta_generic_to_shared(sWhi + r * LDT + cb), g);
            CP16((unsigned)__cvta_generic_to_shared(sWlo + r * LDT + cb), g + K);
        }
        asm volatile("cp.async.commit_group;\n");
    };

    constexpr int WGX = BNp / WN;
    constexpr int MI = WM / 16, NI = WN / 16;
    const int w = tid >> 5;
    const int wy = w / WGX, wx = w % WGX;

    wmma::fragment<wmma::accumulator, 16, 16, 16, float> acc[MI][NI];
#pragma unroll
    for (int i = 0; i < MI; ++i)
#pragma unroll
        for (int j = 0; j < NI; ++j) wmma::fill_fragment(acc[i][j], 0.0f);

#pragma unroll
    for (int s = 0; s < STAGES - 1; ++s) load_stage(s, s);

    for (int c = 0; c < nchunks; ++c) {
        const int cur = c % STAGES;
        if (c + STAGES - 1 < nchunks) {
            load_stage((c + STAGES - 1) % STAGES, c + STAGES - 1);
            asm volatile("cp.async.wait_group %0;\n" :: "n"(STAGES - 1));
        } else {
            asm volatile("cp.async.wait_group 0;\n");
        }
        __syncthreads();

        const __nv_bfloat16* sAhi = smem + cur * STG;
        const __nv_bfloat16* sAlo = sAhi + TA;
        const __nv_bfloat16* sWhi = sAlo + TA;
        const __nv_bfloat16* sWlo = sWhi + TW;

#pragma unroll
        for (int ks = 0; ks < BKT / 16; ++ks) {
            wmma::fragment<wmma::matrix_a, 16, 16, 16, __nv_bfloat16, wmma::row_major> ah[MI], al[MI];
            wmma::fragment<wmma::matrix_b, 16, 16, 16, __nv_bfloat16, wmma::col_major> bh[NI], bl[NI];
#pragma unroll
            for (int i = 0; i < MI; ++i) {
                wmma::load_matrix_sync(ah[i], sAhi + (wy * WM + 16 * i) * LDT + ks * 16, LDT);
                wmma::load_matrix_sync(al[i], sAlo + (wy * WM + 16 * i) * LDT + ks * 16, LDT);
            }
#pragma unroll
            for (int j = 0; j < NI; ++j) {
                wmma::load_matrix_sync(bh[j], sWhi + (wx * WN + 16 * j) * LDT + ks * 16, LDT);
                wmma::load_matrix_sync(bl[j], sWlo + (wx * WN + 16 * j) * LDT + ks * 16, LDT);
            }
#pragma unroll
            for (int i = 0; i < MI; ++i)
#pragma unroll
                for (int j = 0; j < NI; ++j) {
                    wmma::mma_sync(acc[i][j], ah[i], bh[j], acc[i][j]);
                    wmma::mma_sync(acc[i][j], ah[i], bl[j], acc[i][j]);
                    wmma::mma_sync(acc[i][j], al[i], bh[j], acc[i][j]);
                }
        }
        __syncthreads();
    }

    // Epilogue: stage accumulators in smem, then coalesced global work.
    constexpr int LDCc = BNp + 4;
    float* stage = reinterpret_cast<float*>(smem);
#pragma unroll
    for (int i = 0; i < MI; ++i)
#pragma unroll
        for (int j = 0; j < NI; ++j)
            wmma::store_matrix_sync(stage + (wy * WM + 16 * i) * LDCc + wx * WN + 16 * j,
                                    acc[i][j], LDCc, wmma::mem_row_major);
    __syncthreads();

#pragma unroll
    for (int i = 0; i < BMp * BNp / 4 / THREADS; ++i) {
        int f = tid + i * THREADS;
        int row = f / (BNp / 4);
        int c4  = (f % (BNp / 4)) * 4;
        float4 v4 = *reinterpret_cast<float4*>(&stage[row * LDCc + c4]);
        float v[4] = {v4.x, v4.y, v4.z, v4.w};
        long gm = m0 + row;

        if constexpr (EPI == 4) {
            // Reference applies relu to cc BEFORE the gates: cc = relu(x @ W^T).
#pragma unroll
            for (int q = 0; q < 4; ++q) v[q] = fmaxf(v[q], 0.0f);
            // v = {cc_i, cc_f, cc_o, cc_g} for channel s (gate-interleaved W).
            int s = (n0 >> 2) + (f & (BNp / 4 - 1));
            float ig = 1.f / (1.f + expf(-v[0]));
            float fg = 1.f / (1.f + expf(-v[1]));
            float og = 1.f / (1.f + expf(-v[2]));
            float gg = tanhf(v[3]);
            float cold = cell[gm * SS + s];
            float cn = fg * cold + ig * gg;
            cell[gm * SS + s] = cn;
            float h = og * tanhf(cn);
            preds[((long)t * BB + gm) * SS + s] = h;
            __nv_bfloat16* hsr = hs + gm * (2L * KFC);
            split_write(&hsr[s], &hsr[KFC + s], h);
            float rp = h * rW[s];
#pragma unroll
            for (int off = 16; off > 0; off >>= 1)
                rp += __shfl_xor_sync(0xffffffffu, rp, off);
            if ((tid & 31) == 0)
                atomicAdd(&rewards[(long)t * BB + gm], rp);
        } else {
#pragma unroll
            for (int q = 0; q < 4; ++q) {
                if constexpr (EPI == 2 || EPI == 3) v[q] += bias[n0 + c4 + q];
                v[q] = fmaxf(v[q], 0.0f);
            }
            __nv_bfloat16* cp = (__nv_bfloat16*)Cout + gm * (2L * N);
            __nv_bfloat16 h[4]; float lo[4];
#pragma unroll
            for (int q = 0; q < 4; ++q) {
                h[q]  = __float2bfloat16(v[q]);
                lo[q] = v[q] - __bfloat162float(h[q]);
            }
            __nv_bfloat162 hh0; hh0.x = h[0]; hh0.y = h[1];
            __nv_bfloat162 hh1; hh1.x = h[2]; hh1.y = h[3];
            reinterpret_cast<__nv_bfloat162*>(cp + n0 + c4)[0] = hh0;
            reinterpret_cast<__nv_bfloat162*>(cp + n0 + c4)[1] = hh1;
            __nv_bfloat162 ll0; ll0.x = __float2bfloat16(lo[0]); ll0.y = __float2bfloat16(lo[1]);
            __nv_bfloat162 ll1; ll1.x = __float2bfloat16(lo[2]); ll1.y = __float2bfloat16(lo[3]);
            reinterpret_cast<__nv_bfloat162*>(cp + N + n0 + c4)[0] = ll0;
            reinterpret_cast<__nv_bfloat162*>(cp + N + n0 + c4)[1] = ll1;
            if constexpr (EPI == 3) {
                *reinterpret_cast<float4*>(Cdual + gm * N + n0 + c4) =
                    make_float4(v[0], v[1], v[2], v[3]);
            }
        }
    }

    // hs tail (act_t, latent) maintained by the first n-tile CTAs.
    if constexpr (EPI == 4) {
        if (n0 == 0) {
            for (int j = tid; j < BMp * (AA + PP); j += THREADS) {
                int r = j / (AA + PP), q = j % (AA + PP);
                long b = m0 + r;
                float v = (q < AA) ? acts[b * (TT * AA) + t * AA + q]
                                   : latent[b * PP + (q - AA)];
                __nv_bfloat16* hsr = hs + b * (2L * KFC);
                split_write(&hsr[SS + q], &hsr[KFC + SS + q], v);
            }
        }
    }
}

// ---------------------------------------------------------------------------
// Launch
// ---------------------------------------------------------------------------
// Small config: 64x64 tile, 4 warps (32x32 each), 3 stages.
#define SMEM_S (3 * (4 * 64 * LDT) * (int)sizeof(__nv_bfloat16))    // 110592 B
// Big config: 128x128 tile, 8 warps (64x32 each), 3 stages.
#define SMEM_B (3 * (4 * 128 * LDT) * (int)sizeof(__nv_bfloat16))   // 221184 B

extern "C" void kernel_launch(void* const* d_in, const int* /*in_sizes*/, int /*n_in*/,
                              void* d_out, int /*out_size*/) {
    const float* state  = (const float*)d_in[0];
    const float* acts   = (const float*)d_in[1];
    const float* latent = (const float*)d_in[2];
    const float* fcW    = (const float*)d_in[3];
    const float* fcb    = (const float*)d_in[4];
    const float* fc1W   = (const float*)d_in[5];
    const float* fc2W   = (const float*)d_in[6];
    const float* WW     = (const float*)d_in[7];
    const float* rW     = (const float*)d_in[8];
    const float* rb     = (const float*)d_in[9];

    float* preds   = (float*)d_out;
    float* rewards = preds + (long)TT * BB * SS;

    __nv_bfloat16 *fc1e, *fc2b, *WWb, *fcWb, *hb, *x1b, *x2b, *hsb;
    float *cell;
    cudaGetSymbolAddress((void**)&fc1e, g_fc1e);
    cudaGetSymbolAddress((void**)&fc2b, g_fc2b);
    cudaGetSymbolAddress((void**)&WWb,  g_WWb);
    cudaGetSymbolAddress((void**)&fcWb, g_fcWb);
    cudaGetSymbolAddress((void**)&hb,   g_hb);
    cudaGetSymbolAddress((void**)&x1b,  g_x1b);
    cudaGetSymbolAddress((void**)&x2b,  g_x2b);
    cudaGetSymbolAddress((void**)&hsb,  g_hsb);
    cudaGetSymbolAddress((void**)&cell, g_cell);

    cudaFuncSetAttribute((const void*)gemm3<64,64,32,32,128,3,1>,  cudaFuncAttributeMaxDynamicSharedMemorySize, SMEM_S);
    cudaFuncSetAttribute((const void*)gemm3<64,64,32,32,128,3,2>,  cudaFuncAttributeMaxDynamicSharedMemorySize, SMEM_S);
    cudaFuncSetAttribute((const void*)gemm3<64,64,32,32,128,3,3>,  cudaFuncAttributeMaxDynamicSharedMemorySize, SMEM_S);
    cudaFuncSetAttribute((const void*)gemm3<128,128,64,32,256,3,4>, cudaFuncAttributeMaxDynamicSharedMemorySize, SMEM_B);

    // One merged pack/init launch.
    {
        const long total = (long)SS * SS * 2 + (long)S4 * SS + (long)SS * KFC
                         + (long)BB * KFC + (long)TT * BB;
        pack_all<<<(unsigned)((total + 255) / 256), 256>>>(
            fc1W, fc2W, WW, fcW, state, acts, latent, rb, rewards,
            fc1e, fc2b, WWb, fcWb, hsb);
    }

    dim3 gS(SS / 64, BB / 64);      // (32, 4) = 128 CTAs
    dim3 gB(S4 / 128, BB / 128);    // (64, 2) = 128 CTAs

    // hidden = cell = relu(fc(hs0)): one GEMM, dual store
    gemm3<64,64,32,32,128,3,3><<<gS, 128, SMEM_S>>>(
        hsb, fcWb, fcb, hb, cell, SS, KFC,
        nullptr, nullptr, nullptr, nullptr, nullptr, nullptr, nullptr, 0);

    for (int t = 0; t < TT; ++t) {
        gemm3<64,64,32,32,128,3,1><<<gS, 128, SMEM_S>>>(
            hb,  fc1e, nullptr, x1b, nullptr, SS, SS,
            nullptr, nullptr, nullptr, nullptr, nullptr, nullptr, nullptr, 0);
        gemm3<64,64,32,32,128,3,1><<<gS, 128, SMEM_S>>>(
            x1b, fc2b, nullptr, x2b, nullptr, SS, SS,
            nullptr, nullptr, nullptr, nullptr, nullptr, nullptr, nullptr, 0);
        // G3 + fused LSTM gates / reward / hs update
        gemm3<128,128,64,32,256,3,4><<<gB, 256, SMEM_B>>>(
            x2b, WWb, nullptr, nullptr, nullptr, S4, SS,
            cell, rW, rewards, acts, latent, preds, hsb, t);
        if (t + 1 < TT)
            gemm3<64,64,32,32,128,3,2><<<gS, 128, SMEM_S>>>(
                hsb, fcWb, fcb, hb, nullptr, SS, KFC,
                nullptr, nullptr, nullptr, nullptr, nullptr, nullptr, nullptr, 0);
    }
}

// round 10
// speedup vs baseline: 1.0194x; 1.0194x over previous
#include <cuda_runtime.h>
#include <cuda_bf16.h>
#include <mma.h>

using namespace nvcuda;

// Problem constants
#define BB   256
#define TT   32
#define SS   2048
#define AA   64
#define PP   128
#define KFC  (SS + AA + PP)   // 2240
#define S4   (4 * SS)         // 8192

#define BKT  64
#define LDT  (BKT + 8)        // 72 bf16 smem stride

// ---------------------------------------------------------------------------
// Scratch (static device globals; no allocation anywhere)
// ---------------------------------------------------------------------------
__device__ __nv_bfloat16 g_fc1e[(long)SS * 2 * SS];    // fc1_eff packed [hi|lo]
__device__ __nv_bfloat16 g_fc2b[(long)SS * 2 * SS];
__device__ __nv_bfloat16 g_WWb [(long)S4 * 2 * SS];    // gate-interleaved rows: n' = 4s+g
__device__ __nv_bfloat16 g_fcWb[(long)SS * 2 * KFC];
__device__ __nv_bfloat16 g_hb  [(long)BB * 2 * SS];    // carry h, packed
__device__ __nv_bfloat16 g_x1b [(long)BB * 2 * SS];
__device__ __nv_bfloat16 g_x2b [(long)BB * 2 * SS];
__device__ __nv_bfloat16 g_hsb [(long)BB * 2 * KFC];   // cat[h, act, latent], packed
__device__ float         g_cell[(long)BB * SS];

// ---------------------------------------------------------------------------
// Helpers
// ---------------------------------------------------------------------------
__device__ __forceinline__ void split_write(__nv_bfloat16* hi_p, __nv_bfloat16* lo_p, float v) {
    __nv_bfloat16 h = __float2bfloat16(v);
    *hi_p = h;
    *lo_p = __float2bfloat16(v - __bfloat162float(h));
}

// One merged pack/init kernel: fc1_eff, fc2, WW (gate-interleaved), fcW, hs0,
// and rewards initialization (= rb).
__global__ void pack_all(const float* __restrict__ fc1W, const float* __restrict__ fc2W,
                         const float* __restrict__ WW,   const float* __restrict__ fcW,
                         const float* __restrict__ state, const float* __restrict__ acts,
                         const float* __restrict__ latent, const float* __restrict__ rb,
                         float* __restrict__ rewards,
                         __nv_bfloat16* __restrict__ fc1e, __nv_bfloat16* __restrict__ fc2b,
                         __nv_bfloat16* __restrict__ WWb,  __nv_bfloat16* __restrict__ fcWb,
                         __nv_bfloat16* __restrict__ hsb)
{
    const long N1 = (long)SS * SS;
    const long N2 = N1 + (long)SS * SS;
    const long N3 = N2 + (long)S4 * SS;
    const long N4 = N3 + (long)SS * KFC;
    const long N5 = N4 + (long)BB * KFC;
    const long N6 = N5 + (long)TT * BB;
    long idx = (long)blockIdx.x * 256 + threadIdx.x;
    if (idx < N1) {
        long n = idx / SS, k = idx % SS;
        float v = fc1W[n * 2 * SS + k] + fc1W[n * 2 * SS + SS + k];
        split_write(&fc1e[n * 2 * SS + k], &fc1e[n * 2 * SS + SS + k], v);
    } else if (idx < N2) {
        long j = idx - N1;
        long n = j / SS, k = j % SS;
        split_write(&fc2b[n * 2 * SS + k], &fc2b[n * 2 * SS + SS + k], fc2W[j]);
    } else if (idx < N3) {
        long j = idx - N2;
        long np = j / SS, k = j % SS;            // np = interleaved row
        long g = np & 3, s = np >> 2;            // src row = g*SS + s
        float v = WW[(g * SS + s) * SS + k];
        split_write(&WWb[np * 2 * SS + k], &WWb[np * 2 * SS + SS + k], v);
    } else if (idx < N4) {
        long j = idx - N3;
        long n = j / KFC, k = j % KFC;
        split_write(&fcWb[n * 2 * KFC + k], &fcWb[n * 2 * KFC + KFC + k], fcW[j]);
    } else if (idx < N5) {
        long j = idx - N4;
        int b = (int)(j / KFC), q = (int)(j % KFC);
        float v;
        if (q < SS)            v = state[(long)b * SS + q];
        else if (q < SS + AA)  v = acts[(long)b * (TT * AA) + (q - SS)];
        else                   v = latent[(long)b * PP + (q - SS - AA)];
        split_write(&hsb[(long)b * 2 * KFC + q], &hsb[(long)b * 2 * KFC + KFC + q], v);
    } else if (idx < N6) {
        rewards[idx - N5] = rb[0];
    }
}

// ---------------------------------------------------------------------------
// Split-bf16 GEMM (Ozaki 3-term):  C[256, N] = A[256,K] @ W[N,K]^T
// A, W packed [.,2K] bf16 [hi|lo]; per 64-K chunk: Ah*Wh + Ah*Wl + Al*Wh.
// EPI: 1 relu+split-bf16 store; 2 bias+relu+split-bf16; 3 = 2 + fp32 dual;
//      4 = fused LSTM gates epilogue (W gate-interleaved; relu(cc) then gates;
//          writes cell/preds/hsb/rewards; no C store).
// ---------------------------------------------------------------------------
#define CP16(s, g) asm volatile("cp.async.cg.shared.global [%0], [%1], 16;\n" :: "r"(s), "l"(g))

template<int BMp, int BNp, int WM, int WN, int THREADS, int STAGES, int EPI>
__global__ __launch_bounds__(THREADS, 1)
void gemm3(const __nv_bfloat16* __restrict__ Ab,
           const __nv_bfloat16* __restrict__ Wb,
           const float* __restrict__ bias,
           void* __restrict__ Cout,
           float* __restrict__ Cdual,
           int N, int K,
           float* __restrict__ cell,
           const float* __restrict__ rW,
           float* __restrict__ rewards,
           const float* __restrict__ acts,
           const float* __restrict__ latent,
           float* __restrict__ preds,
           __nv_bfloat16* __restrict__ hs,
           int t)
{
    extern __shared__ __align__(16) __nv_bfloat16 smem[];
    constexpr int TA = BMp * LDT;
    constexpr int TW = BNp * LDT;
    constexpr int STG = 2 * TA + 2 * TW;   // elements per stage

    const int tid = threadIdx.x;
    const int m0 = blockIdx.y * BMp;
    const int n0 = blockIdx.x * BNp;
    const int lda = 2 * K;
    const int nchunks = K / BKT;

    auto load_stage = [&](int buf, int c) {
        const int kb = c * BKT;
        __nv_bfloat16* sAhi = smem + buf * STG;
        __nv_bfloat16* sAlo = sAhi + TA;
        __nv_bfloat16* sWhi = sAlo + TA;
        __nv_bfloat16* sWlo = sWhi + TW;
#pragma unroll
        for (int i = 0; i < BMp * 8 / THREADS; ++i) {
            int f = tid + i * THREADS;
            int r = f >> 3, cb = (f & 7) * 8;
            const __nv_bfloat16* g = Ab + (long)(m0 + r) * lda + kb + cb;
            CP16((unsigned)__cvta_generic_to_shared(sAhi + r * LDT + cb), g);
            CP16((unsigned)__cvta_generic_to_shared(sAlo + r * LDT + cb), g + K);
        }
#pragma unroll
        for (int i = 0; i < BNp * 8 / THREADS; ++i) {
            int f = tid + i * THREADS;
            int r = f >> 3, cb = (f & 7) * 8;
            const __nv_bfloat16* g = Wb + (long)(n0 + r) * lda + kb + cb;
            CP16((unsigned)__cvta_generic_to_shared(sWhi + r * LDT + cb), g);
            CP16((unsigned)__cvta_generic_to_shared(sWlo + r * LDT + cb), g + K);
        }
        asm volatile("cp.async.commit_group;\n");
    };

    constexpr int WGX = BNp / WN;
    constexpr int MI = WM / 16, NI = WN / 16;
    const int w = tid >> 5;
    const int wy = w / WGX, wx = w % WGX;

    wmma::fragment<wmma::accumulator, 16, 16, 16, float> acc[MI][NI];
#pragma unroll
    for (int i = 0; i < MI; ++i)
#pragma unroll
        for (int j = 0; j < NI; ++j) wmma::fill_fragment(acc[i][j], 0.0f);

#pragma unroll
    for (int s = 0; s < STAGES - 1; ++s) load_stage(s, s);

    for (int c = 0; c < nchunks; ++c) {
        const int cur = c % STAGES;
        if (c + STAGES - 1 < nchunks) {
            load_stage((c + STAGES - 1) % STAGES, c + STAGES - 1);
            asm volatile("cp.async.wait_group %0;\n" :: "n"(STAGES - 1));
        } else {
            asm volatile("cp.async.wait_group 0;\n");
        }
        __syncthreads();

        const __nv_bfloat16* sAhi = smem + cur * STG;
        const __nv_bfloat16* sAlo = sAhi + TA;
        const __nv_bfloat16* sWhi = sAlo + TA;
        const __nv_bfloat16* sWlo = sWhi + TW;

#pragma unroll
        for (int ks = 0; ks < BKT / 16; ++ks) {
            wmma::fragment<wmma::matrix_a, 16, 16, 16, __nv_bfloat16, wmma::row_major> ah[MI], al[MI];
            wmma::fragment<wmma::matrix_b, 16, 16, 16, __nv_bfloat16, wmma::col_major> bh[NI], bl[NI];
#pragma unroll
            for (int i = 0; i < MI; ++i) {
                wmma::load_matrix_sync(ah[i], sAhi + (wy * WM + 16 * i) * LDT + ks * 16, LDT);
                wmma::load_matrix_sync(al[i], sAlo + (wy * WM + 16 * i) * LDT + ks * 16, LDT);
            }
#pragma unroll
            for (int j = 0; j < NI; ++j) {
                wmma::load_matrix_sync(bh[j], sWhi + (wx * WN + 16 * j) * LDT + ks * 16, LDT);
                wmma::load_matrix_sync(bl[j], sWlo + (wx * WN + 16 * j) * LDT + ks * 16, LDT);
            }
#pragma unroll
            for (int i = 0; i < MI; ++i)
#pragma unroll
                for (int j = 0; j < NI; ++j) {
                    wmma::mma_sync(acc[i][j], ah[i], bh[j], acc[i][j]);
                    wmma::mma_sync(acc[i][j], ah[i], bl[j], acc[i][j]);
                    wmma::mma_sync(acc[i][j], al[i], bh[j], acc[i][j]);
                }
        }
        __syncthreads();
    }

    // Epilogue: stage accumulators in smem, then coalesced global work.
    constexpr int LDCc = BNp + 4;
    float* stage = reinterpret_cast<float*>(smem);
#pragma unroll
    for (int i = 0; i < MI; ++i)
#pragma unroll
        for (int j = 0; j < NI; ++j)
            wmma::store_matrix_sync(stage + (wy * WM + 16 * i) * LDCc + wx * WN + 16 * j,
                                    acc[i][j], LDCc, wmma::mem_row_major);
    __syncthreads();

#pragma unroll
    for (int i = 0; i < BMp * BNp / 4 / THREADS; ++i) {
        int f = tid + i * THREADS;
        int row = f / (BNp / 4);
        int c4  = (f % (BNp / 4)) * 4;
        float4 v4 = *reinterpret_cast<float4*>(&stage[row * LDCc + c4]);
        float v[4] = {v4.x, v4.y, v4.z, v4.w};
        long gm = m0 + row;

        if constexpr (EPI == 4) {
            // Reference applies relu to cc BEFORE the gates: cc = relu(x @ W^T).
#pragma unroll
            for (int q = 0; q < 4; ++q) v[q] = fmaxf(v[q], 0.0f);
            // v = {cc_i, cc_f, cc_o, cc_g} for channel s (gate-interleaved W).
            int s = (n0 >> 2) + (f & (BNp / 4 - 1));
            float ig = 1.f / (1.f + expf(-v[0]));
            float fg = 1.f / (1.f + expf(-v[1]));
            float og = 1.f / (1.f + expf(-v[2]));
            float gg = tanhf(v[3]);
            float cold = cell[gm * SS + s];
            float cn = fg * cold + ig * gg;
            cell[gm * SS + s] = cn;
            float h = og * tanhf(cn);
            preds[((long)t * BB + gm) * SS + s] = h;
            __nv_bfloat16* hsr = hs + gm * (2L * KFC);
            split_write(&hsr[s], &hsr[KFC + s], h);
            float rp = h * rW[s];
#pragma unroll
            for (int off = 16; off > 0; off >>= 1)
                rp += __shfl_xor_sync(0xffffffffu, rp, off);
            if ((tid & 31) == 0)
                atomicAdd(&rewards[(long)t * BB + gm], rp);
        } else {
#pragma unroll
            for (int q = 0; q < 4; ++q) {
                if constexpr (EPI == 2 || EPI == 3) v[q] += bias[n0 + c4 + q];
                v[q] = fmaxf(v[q], 0.0f);
            }
            __nv_bfloat16* cp = (__nv_bfloat16*)Cout + gm * (2L * N);
            __nv_bfloat16 h[4]; float lo[4];
#pragma unroll
            for (int q = 0; q < 4; ++q) {
                h[q]  = __float2bfloat16(v[q]);
                lo[q] = v[q] - __bfloat162float(h[q]);
            }
            __nv_bfloat162 hh0; hh0.x = h[0]; hh0.y = h[1];
            __nv_bfloat162 hh1; hh1.x = h[2]; hh1.y = h[3];
            reinterpret_cast<__nv_bfloat162*>(cp + n0 + c4)[0] = hh0;
            reinterpret_cast<__nv_bfloat162*>(cp + n0 + c4)[1] = hh1;
            __nv_bfloat162 ll0; ll0.x = __float2bfloat16(lo[0]); ll0.y = __float2bfloat16(lo[1]);
            __nv_bfloat162 ll1; ll1.x = __float2bfloat16(lo[2]); ll1.y = __float2bfloat16(lo[3]);
            reinterpret_cast<__nv_bfloat162*>(cp + N + n0 + c4)[0] = ll0;
            reinterpret_cast<__nv_bfloat162*>(cp + N + n0 + c4)[1] = ll1;
            if constexpr (EPI == 3) {
                *reinterpret_cast<float4*>(Cdual + gm * N + n0 + c4) =
                    make_float4(v[0], v[1], v[2], v[3]);
            }
        }
    }

    // hs tail (act_t, latent): distributed — each of the 64 n-CTAs writes a
    // 3-column slice of the 192 tail columns for its 128 rows.
    if constexpr (EPI == 4) {
        const int ncta = (int)gridDim.x;              // 64
        const int cols = (AA + PP) / 64;              // 3 (assumes 64 n-CTAs)
        const int q0 = (int)blockIdx.x * cols;
        (void)ncta;
        for (int j = tid; j < BMp * cols; j += THREADS) {
            int r = j / cols, qq = j % cols;
            int q = q0 + qq;
            long b = m0 + r;
            float v = (q < AA) ? acts[b * (TT * AA) + t * AA + q]
                               : latent[b * PP + (q - AA)];
            __nv_bfloat16* hsr = hs + b * (2L * KFC);
            split_write(&hsr[SS + q], &hsr[KFC + SS + q], v);
        }
    }
}

// ---------------------------------------------------------------------------
// Launch
// ---------------------------------------------------------------------------
// Small config: 64x64 tile, 8 warps (16x32 each), 3 stages, 256 threads.
#define SMEM_S (3 * (4 * 64 * LDT) * (int)sizeof(__nv_bfloat16))    // 110592 B
// Big config: 128x128 tile, 8 warps (64x32 each), 2 stages, 256 threads.
#define SMEM_B (2 * (4 * 128 * LDT) * (int)sizeof(__nv_bfloat16))   // 147456 B

extern "C" void kernel_launch(void* const* d_in, const int* /*in_sizes*/, int /*n_in*/,
                              void* d_out, int /*out_size*/) {
    const float* state  = (const float*)d_in[0];
    const float* acts   = (const float*)d_in[1];
    const float* latent = (const float*)d_in[2];
    const float* fcW    = (const float*)d_in[3];
    const float* fcb    = (const float*)d_in[4];
    const float* fc1W   = (const float*)d_in[5];
    const float* fc2W   = (const float*)d_in[6];
    const float* WW     = (const float*)d_in[7];
    const float* rW     = (const float*)d_in[8];
    const float* rb     = (const float*)d_in[9];

    float* preds   = (float*)d_out;
    float* rewards = preds + (long)TT * BB * SS;

    __nv_bfloat16 *fc1e, *fc2b, *WWb, *fcWb, *hb, *x1b, *x2b, *hsb;
    float *cell;
    cudaGetSymbolAddress((void**)&fc1e, g_fc1e);
    cudaGetSymbolAddress((void**)&fc2b, g_fc2b);
    cudaGetSymbolAddress((void**)&WWb,  g_WWb);
    cudaGetSymbolAddress((void**)&fcWb, g_fcWb);
    cudaGetSymbolAddress((void**)&hb,   g_hb);
    cudaGetSymbolAddress((void**)&x1b,  g_x1b);
    cudaGetSymbolAddress((void**)&x2b,  g_x2b);
    cudaGetSymbolAddress((void**)&hsb,  g_hsb);
    cudaGetSymbolAddress((void**)&cell, g_cell);

    cudaFuncSetAttribute((const void*)gemm3<64,64,16,32,256,3,1>,  cudaFuncAttributeMaxDynamicSharedMemorySize, SMEM_S);
    cudaFuncSetAttribute((const void*)gemm3<64,64,16,32,256,3,2>,  cudaFuncAttributeMaxDynamicSharedMemorySize, SMEM_S);
    cudaFuncSetAttribute((const void*)gemm3<64,64,16,32,256,3,3>,  cudaFuncAttributeMaxDynamicSharedMemorySize, SMEM_S);
    cudaFuncSetAttribute((const void*)gemm3<128,128,64,32,256,2,4>, cudaFuncAttributeMaxDynamicSharedMemorySize, SMEM_B);

    // One merged pack/init launch.
    {
        const long total = (long)SS * SS * 2 + (long)S4 * SS + (long)SS * KFC
                         + (long)BB * KFC + (long)TT * BB;
        pack_all<<<(unsigned)((total + 255) / 256), 256>>>(
            fc1W, fc2W, WW, fcW, state, acts, latent, rb, rewards,
            fc1e, fc2b, WWb, fcWb, hsb);
    }

    dim3 gS(SS / 64, BB / 64);      // (32, 4) = 128 CTAs
    dim3 gB(S4 / 128, BB / 128);    // (64, 2) = 128 CTAs

    // hidden = cell = relu(fc(hs0)): one GEMM, dual store
    gemm3<64,64,16,32,256,3,3><<<gS, 256, SMEM_S>>>(
        hsb, fcWb, fcb, hb, cell, SS, KFC,
        nullptr, nullptr, nullptr, nullptr, nullptr, nullptr, nullptr, 0);

    for (int t = 0; t < TT; ++t) {
        gemm3<64,64,16,32,256,3,1><<<gS, 256, SMEM_S>>>(
            hb,  fc1e, nullptr, x1b, nullptr, SS, SS,
            nullptr, nullptr, nullptr, nullptr, nullptr, nullptr, nullptr, 0);
        gemm3<64,64,16,32,256,3,1><<<gS, 256, SMEM_S>>>(
            x1b, fc2b, nullptr, x2b, nullptr, SS, SS,
            nullptr, nullptr, nullptr, nullptr, nullptr, nullptr, nullptr, 0);
        // G3 + fused LSTM gates / reward / hs update
        gemm3<128,128,64,32,256,2,4><<<gB, 256, SMEM_B>>>(
            x2b, WWb, nullptr, nullptr, nullptr, S4, SS,
            cell, rW, rewards, acts, latent, preds, hsb, t);
        if (t + 1 < TT)
            gemm3<64,64,16,32,256,3,2><<<gS, 256, SMEM_S>>>(
                hsb, fcWb, fcb, hb, nullptr, SS, KFC,
                nullptr, nullptr, nullptr, nullptr, nullptr, nullptr, nullptr, 0);
    }
}

// round 11
// speedup vs baseline: 1.0809x; 1.0604x over previous
#include <cuda_runtime.h>
#include <cuda_bf16.h>
#include <mma.h>

using namespace nvcuda;

// Problem constants
#define BB   256
#define TT   32
#define SS   2048
#define AA   64
#define PP   128
#define KFC  (SS + AA + PP)   // 2240
#define S4   (4 * SS)         // 8192

#define BKT  64
#define LDT  (BKT + 8)        // 72 bf16 smem stride

// ---------------------------------------------------------------------------
// Scratch (static device globals; no allocation anywhere)
// ---------------------------------------------------------------------------
__device__ __nv_bfloat16 g_fc1e[(long)SS * 2 * SS];    // fc1_eff packed [hi|lo]
__device__ __nv_bfloat16 g_fc2b[(long)SS * 2 * SS];
__device__ __nv_bfloat16 g_WWb [(long)S4 * 2 * SS];    // gate-interleaved rows: n' = 4s+g
__device__ __nv_bfloat16 g_fcWb[(long)SS * 2 * KFC];
__device__ __nv_bfloat16 g_hb  [(long)BB * 2 * SS];    // carry h, packed
__device__ __nv_bfloat16 g_x1b [(long)BB * 2 * SS];
__device__ __nv_bfloat16 g_x2b [(long)BB * 2 * SS];
__device__ __nv_bfloat16 g_hsb [(long)BB * 2 * KFC];   // cat[h, act, latent], packed
__device__ float         g_cell[(long)BB * SS];
__device__ float         g_part[(long)BB * SS];        // split-K fp32 partials
__device__ int           g_flags[256];                 // split-K epoch flags (zero-init)

// ---------------------------------------------------------------------------
// Helpers
// ---------------------------------------------------------------------------
__device__ __forceinline__ void split_write(__nv_bfloat16* hi_p, __nv_bfloat16* lo_p, float v) {
    __nv_bfloat16 h = __float2bfloat16(v);
    *hi_p = h;
    *lo_p = __float2bfloat16(v - __bfloat162float(h));
}

__device__ __forceinline__ int ld_acq(const int* p) {
    int v;
    asm volatile("ld.acquire.gpu.global.b32 %0, [%1];" : "=r"(v) : "l"(p) : "memory");
    return v;
}
__device__ __forceinline__ void st_rel(int* p, int v) {
    asm volatile("st.release.gpu.global.b32 [%0], %1;" :: "l"(p), "r"(v) : "memory");
}

// One merged pack/init kernel: fc1_eff, fc2, WW (gate-interleaved), fcW, hs0,
// and rewards initialization (= rb).
__global__ void pack_all(const float* __restrict__ fc1W, const float* __restrict__ fc2W,
                         const float* __restrict__ WW,   const float* __restrict__ fcW,
                         const float* __restrict__ state, const float* __restrict__ acts,
                         const float* __restrict__ latent, const float* __restrict__ rb,
                         float* __restrict__ rewards,
                         __nv_bfloat16* __restrict__ fc1e, __nv_bfloat16* __restrict__ fc2b,
                         __nv_bfloat16* __restrict__ WWb,  __nv_bfloat16* __restrict__ fcWb,
                         __nv_bfloat16* __restrict__ hsb)
{
    const long N1 = (long)SS * SS;
    const long N2 = N1 + (long)SS * SS;
    const long N3 = N2 + (long)S4 * SS;
    const long N4 = N3 + (long)SS * KFC;
    const long N5 = N4 + (long)BB * KFC;
    const long N6 = N5 + (long)TT * BB;
    long idx = (long)blockIdx.x * 256 + threadIdx.x;
    if (idx < N1) {
        long n = idx / SS, k = idx % SS;
        float v = fc1W[n * 2 * SS + k] + fc1W[n * 2 * SS + SS + k];
        split_write(&fc1e[n * 2 * SS + k], &fc1e[n * 2 * SS + SS + k], v);
    } else if (idx < N2) {
        long j = idx - N1;
        long n = j / SS, k = j % SS;
        split_write(&fc2b[n * 2 * SS + k], &fc2b[n * 2 * SS + SS + k], fc2W[j]);
    } else if (idx < N3) {
        long j = idx - N2;
        long np = j / SS, k = j % SS;            // np = interleaved row
        long g = np & 3, s = np >> 2;            // src row = g*SS + s
        float v = WW[(g * SS + s) * SS + k];
        split_write(&WWb[np * 2 * SS + k], &WWb[np * 2 * SS + SS + k], v);
    } else if (idx < N4) {
        long j = idx - N3;
        long n = j / KFC, k = j % KFC;
        split_write(&fcWb[n * 2 * KFC + k], &fcWb[n * 2 * KFC + KFC + k], fcW[j]);
    } else if (idx < N5) {
        long j = idx - N4;
        int b = (int)(j / KFC), q = (int)(j % KFC);
        float v;
        if (q < SS)            v = state[(long)b * SS + q];
        else if (q < SS + AA)  v = acts[(long)b * (TT * AA) + (q - SS)];
        else                   v = latent[(long)b * PP + (q - SS - AA)];
        split_write(&hsb[(long)b * 2 * KFC + q], &hsb[(long)b * 2 * KFC + KFC + q], v);
    } else if (idx < N6) {
        rewards[idx - N5] = rb[0];
    }
}

// ---------------------------------------------------------------------------
// Split-bf16 GEMM (Ozaki 3-term):  C[256, N] = A[256,K] @ W[N,K]^T
// A, W packed [.,2K] bf16 [hi|lo]; per 64-K chunk: Ah*Wh + Ah*Wl + Al*Wh.
// EPI: 1 relu+split-bf16 store; 2 bias+relu+split-bf16; 3 = 2 + fp32 dual;
//      4 = fused LSTM gates epilogue.
// SPLITK=1: grid.z=2, z=1 computes the upper K-half and publishes an fp32
// partial (epoch flag); z=0 computes the lower half (+1 chunk for odd K),
// spins on the flag, combines, and runs the epilogue.
// ---------------------------------------------------------------------------
#define CP16(s, g) asm volatile("cp.async.cg.shared.global [%0], [%1], 16;\n" :: "r"(s), "l"(g))

template<int BMp, int BNp, int WM, int WN, int THREADS, int STAGES, int EPI, int SPLITK>
__global__ __launch_bounds__(THREADS, 1)
void gemm3(const __nv_bfloat16* __restrict__ Ab,
           const __nv_bfloat16* __restrict__ Wb,
           const float* __restrict__ bias,
           void* __restrict__ Cout,
           float* __restrict__ Cdual,
           int N, int K,
           float* __restrict__ cell,
           const float* __restrict__ rW,
           float* __restrict__ rewards,
           const float* __restrict__ acts,
           const float* __restrict__ latent,
           float* __restrict__ preds,
           __nv_bfloat16* __restrict__ hs,
           int t, int epoch)
{
    extern __shared__ __align__(16) __nv_bfloat16 smem[];
    constexpr int TA = BMp * LDT;
    constexpr int TW = BNp * LDT;
    constexpr int STG = 2 * TA + 2 * TW;   // elements per stage

    const int tid = threadIdx.x;
    const int m0 = blockIdx.y * BMp;
    const int n0 = blockIdx.x * BNp;
    const int lda = 2 * K;

    const int ctot = K / BKT;
    int cbeg = 0, cend = ctot;
    if constexpr (SPLITK) {
        const int c0 = (ctot + 1) / 2;
        if (blockIdx.z == 0) cend = c0; else cbeg = c0;
    }
    const int nch = cend - cbeg;

    auto load_stage = [&](int buf, int c) {
        const int kb = c * BKT;
        __nv_bfloat16* sAhi = smem + buf * STG;
        __nv_bfloat16* sAlo = sAhi + TA;
        __nv_bfloat16* sWhi = sAlo + TA;
        __nv_bfloat16* sWlo = sWhi + TW;
#pragma unroll
        for (int i = 0; i < BMp * 8 / THREADS; ++i) {
            int f = tid + i * THREADS;
            int r = f >> 3, cb = (f & 7) * 8;
            const __nv_bfloat16* g = Ab + (long)(m0 + r) * lda + kb + cb;
            CP16((unsigned)__cvta_generic_to_shared(sAhi + r * LDT + cb), g);
            CP16((unsigned)__cvta_generic_to_shared(sAlo + r * LDT + cb), g + K);
        }
#pragma unroll
        for (int i = 0; i < BNp * 8 / THREADS; ++i) {
            int f = tid + i * THREADS;
            int r = f >> 3, cb = (f & 7) * 8;
            const __nv_bfloat16* g = Wb + (long)(n0 + r) * lda + kb + cb;
            CP16((unsigned)__cvta_generic_to_shared(sWhi + r * LDT + cb), g);
            CP16((unsigned)__cvta_generic_to_shared(sWlo + r * LDT + cb), g + K);
        }
        asm volatile("cp.async.commit_group;\n");
    };

    constexpr int WGX = BNp / WN;
    constexpr int MI = WM / 16, NI = WN / 16;
    const int w = tid >> 5;
    const int wy = w / WGX, wx = w % WGX;

    wmma::fragment<wmma::accumulator, 16, 16, 16, float> acc[MI][NI];
#pragma unroll
    for (int i = 0; i < MI; ++i)
#pragma unroll
        for (int j = 0; j < NI; ++j) wmma::fill_fragment(acc[i][j], 0.0f);

#pragma unroll
    for (int s = 0; s < STAGES - 1; ++s)
        if (s < nch) load_stage(s % STAGES, cbeg + s);

    for (int r = 0; r < nch; ++r) {
        const int cur = r % STAGES;
        if (r + STAGES - 1 < nch) {
            load_stage((r + STAGES - 1) % STAGES, cbeg + r + STAGES - 1);
            asm volatile("cp.async.wait_group %0;\n" :: "n"(STAGES - 1));
        } else {
            asm volatile("cp.async.wait_group 0;\n");
        }
        __syncthreads();

        const __nv_bfloat16* sAhi = smem + cur * STG;
        const __nv_bfloat16* sAlo = sAhi + TA;
        const __nv_bfloat16* sWhi = sAlo + TA;
        const __nv_bfloat16* sWlo = sWhi + TW;

#pragma unroll
        for (int ks = 0; ks < BKT / 16; ++ks) {
            wmma::fragment<wmma::matrix_a, 16, 16, 16, __nv_bfloat16, wmma::row_major> ah[MI], al[MI];
            wmma::fragment<wmma::matrix_b, 16, 16, 16, __nv_bfloat16, wmma::col_major> bh[NI], bl[NI];
#pragma unroll
            for (int i = 0; i < MI; ++i) {
                wmma::load_matrix_sync(ah[i], sAhi + (wy * WM + 16 * i) * LDT + ks * 16, LDT);
                wmma::load_matrix_sync(al[i], sAlo + (wy * WM + 16 * i) * LDT + ks * 16, LDT);
            }
#pragma unroll
            for (int j = 0; j < NI; ++j) {
                wmma::load_matrix_sync(bh[j], sWhi + (wx * WN + 16 * j) * LDT + ks * 16, LDT);
                wmma::load_matrix_sync(bl[j], sWlo + (wx * WN + 16 * j) * LDT + ks * 16, LDT);
            }
#pragma unroll
            for (int i = 0; i < MI; ++i)
#pragma unroll
                for (int j = 0; j < NI; ++j) {
                    wmma::mma_sync(acc[i][j], ah[i], bh[j], acc[i][j]);
                    wmma::mma_sync(acc[i][j], ah[i], bl[j], acc[i][j]);
                    wmma::mma_sync(acc[i][j], al[i], bh[j], acc[i][j]);
                }
        }
        __syncthreads();
    }

    // Stage accumulators in smem.
    constexpr int LDCc = BNp + 4;
    float* stage = reinterpret_cast<float*>(smem);
#pragma unroll
    for (int i = 0; i < MI; ++i)
#pragma unroll
        for (int j = 0; j < NI; ++j)
            wmma::store_matrix_sync(stage + (wy * WM + 16 * i) * LDCc + wx * WN + 16 * j,
                                    acc[i][j], LDCc, wmma::mem_row_major);
    __syncthreads();

    int* flagp = nullptr;
    if constexpr (SPLITK) {
        flagp = &g_flags[blockIdx.y * gridDim.x + blockIdx.x];
        if (blockIdx.z == 1) {
            // Producer: publish fp32 partial, release flag, exit.
#pragma unroll
            for (int i = 0; i < BMp * BNp / 4 / THREADS; ++i) {
                int f = tid + i * THREADS;
                int row = f / (BNp / 4);
                int c4  = (f % (BNp / 4)) * 4;
                float4 v4 = *reinterpret_cast<float4*>(&stage[row * LDCc + c4]);
                *reinterpret_cast<float4*>(&g_part[(long)(m0 + row) * N + n0 + c4]) = v4;
            }
            __threadfence();
            __syncthreads();
            if (tid == 0) st_rel(flagp, epoch);
            return;
        }
        // Combiner: wait for producer.
        if (tid == 0) {
            while (ld_acq(flagp) != epoch) __nanosleep(32);
        }
        __syncthreads();
    }

#pragma unroll
    for (int i = 0; i < BMp * BNp / 4 / THREADS; ++i) {
        int f = tid + i * THREADS;
        int row = f / (BNp / 4);
        int c4  = (f % (BNp / 4)) * 4;
        float4 v4 = *reinterpret_cast<float4*>(&stage[row * LDCc + c4]);
        float v[4] = {v4.x, v4.y, v4.z, v4.w};
        long gm = m0 + row;

        if constexpr (SPLITK) {
            float4 p4 = *reinterpret_cast<const float4*>(&g_part[gm * (long)N + n0 + c4]);
            v[0] += p4.x; v[1] += p4.y; v[2] += p4.z; v[3] += p4.w;
        }

        if constexpr (EPI == 4) {
            // Reference applies relu to cc BEFORE the gates: cc = relu(x @ W^T).
#pragma unroll
            for (int q = 0; q < 4; ++q) v[q] = fmaxf(v[q], 0.0f);
            // v = {cc_i, cc_f, cc_o, cc_g} for channel s (gate-interleaved W).
            int s = (n0 >> 2) + (f & (BNp / 4 - 1));
            float ig = 1.f / (1.f + expf(-v[0]));
            float fg = 1.f / (1.f + expf(-v[1]));
            float og = 1.f / (1.f + expf(-v[2]));
            float gg = tanhf(v[3]);
            float cold = cell[gm * SS + s];
            float cn = fg * cold + ig * gg;
            cell[gm * SS + s] = cn;
            float h = og * tanhf(cn);
            preds[((long)t * BB + gm) * SS + s] = h;
            __nv_bfloat16* hsr = hs + gm * (2L * KFC);
            split_write(&hsr[s], &hsr[KFC + s], h);
            float rp = h * rW[s];
            constexpr int SEG = BNp / 4 < 32 ? BNp / 4 : 32;
#pragma unroll
            for (int off = SEG / 2; off > 0; off >>= 1)
                rp += __shfl_xor_sync(0xffffffffu, rp, off);
            if ((tid & (SEG - 1)) == 0)
                atomicAdd(&rewards[(long)t * BB + gm], rp);
        } else {
#pragma unroll
            for (int q = 0; q < 4; ++q) {
                if constexpr (EPI == 2 || EPI == 3) v[q] += bias[n0 + c4 + q];
                v[q] = fmaxf(v[q], 0.0f);
            }
            __nv_bfloat16* cp = (__nv_bfloat16*)Cout + gm * (2L * N);
            __nv_bfloat16 h[4]; float lo[4];
#pragma unroll
            for (int q = 0; q < 4; ++q) {
                h[q]  = __float2bfloat16(v[q]);
                lo[q] = v[q] - __bfloat162float(h[q]);
            }
            __nv_bfloat162 hh0; hh0.x = h[0]; hh0.y = h[1];
            __nv_bfloat162 hh1; hh1.x = h[2]; hh1.y = h[3];
            reinterpret_cast<__nv_bfloat162*>(cp + n0 + c4)[0] = hh0;
            reinterpret_cast<__nv_bfloat162*>(cp + n0 + c4)[1] = hh1;
            __nv_bfloat162 ll0; ll0.x = __float2bfloat16(lo[0]); ll0.y = __float2bfloat16(lo[1]);
            __nv_bfloat162 ll1; ll1.x = __float2bfloat16(lo[2]); ll1.y = __float2bfloat16(lo[3]);
            reinterpret_cast<__nv_bfloat162*>(cp + N + n0 + c4)[0] = ll0;
            reinterpret_cast<__nv_bfloat162*>(cp + N + n0 + c4)[1] = ll1;
            if constexpr (EPI == 3) {
                *reinterpret_cast<float4*>(Cdual + gm * N + n0 + c4) =
                    make_float4(v[0], v[1], v[2], v[3]);
            }
        }
    }

    if constexpr (SPLITK) {
        if (tid == 0) *flagp = 0;   // reset for next epoch (ordered by kernel boundary)
    }

    // hs tail (act_t, latent): distributed across the G3 n-CTAs.
    if constexpr (EPI == 4) {
        const int cols = (AA + PP) / 64;              // 3 (gridDim.x == 64)
        const int q0 = (int)blockIdx.x * cols;
        for (int j = tid; j < BMp * cols; j += THREADS) {
            int r = j / cols, qq = j % cols;
            int q = q0 + qq;
            long b = m0 + r;
            float v = (q < AA) ? acts[b * (TT * AA) + t * AA + q]
                               : latent[b * PP + (q - AA)];
            __nv_bfloat16* hsr = hs + b * (2L * KFC);
            split_write(&hsr[SS + q], &hsr[KFC + SS + q], v);
        }
    }
}

// ---------------------------------------------------------------------------
// Launch
// ---------------------------------------------------------------------------
// Small config: 64x64 tile, 4 warps (32x32), 2 stages, split-K2 -> 2 CTA/SM.
#define SMEM_S (2 * (4 * 64 * LDT) * (int)sizeof(__nv_bfloat16))    // 73728 B
// Big config: 128x128 tile, 8 warps (64x32), 2 stages.
#define SMEM_B (2 * (4 * 128 * LDT) * (int)sizeof(__nv_bfloat16))   // 147456 B

extern "C" void kernel_launch(void* const* d_in, const int* /*in_sizes*/, int /*n_in*/,
                              void* d_out, int /*out_size*/) {
    const float* state  = (const float*)d_in[0];
    const float* acts   = (const float*)d_in[1];
    const float* latent = (const float*)d_in[2];
    const float* fcW    = (const float*)d_in[3];
    const float* fcb    = (const float*)d_in[4];
    const float* fc1W   = (const float*)d_in[5];
    const float* fc2W   = (const float*)d_in[6];
    const float* WW     = (const float*)d_in[7];
    const float* rW     = (const float*)d_in[8];
    const float* rb     = (const float*)d_in[9];

    float* preds   = (float*)d_out;
    float* rewards = preds + (long)TT * BB * SS;

    __nv_bfloat16 *fc1e, *fc2b, *WWb, *fcWb, *hb, *x1b, *x2b, *hsb;
    float *cell;
    cudaGetSymbolAddress((void**)&fc1e, g_fc1e);
    cudaGetSymbolAddress((void**)&fc2b, g_fc2b);
    cudaGetSymbolAddress((void**)&WWb,  g_WWb);
    cudaGetSymbolAddress((void**)&fcWb, g_fcWb);
    cudaGetSymbolAddress((void**)&hb,   g_hb);
    cudaGetSymbolAddress((void**)&x1b,  g_x1b);
    cudaGetSymbolAddress((void**)&x2b,  g_x2b);
    cudaGetSymbolAddress((void**)&hsb,  g_hsb);
    cudaGetSymbolAddress((void**)&cell, g_cell);

    cudaFuncSetAttribute((const void*)gemm3<64,64,32,32,128,2,1,1>,  cudaFuncAttributeMaxDynamicSharedMemorySize, SMEM_S);
    cudaFuncSetAttribute((const void*)gemm3<64,64,32,32,128,2,2,1>,  cudaFuncAttributeMaxDynamicSharedMemorySize, SMEM_S);
    cudaFuncSetAttribute((const void*)gemm3<64,64,32,32,128,2,3,1>,  cudaFuncAttributeMaxDynamicSharedMemorySize, SMEM_S);
    cudaFuncSetAttribute((const void*)gemm3<128,128,64,32,256,2,4,0>, cudaFuncAttributeMaxDynamicSharedMemorySize, SMEM_B);

    // One merged pack/init launch.
    {
        const long total = (long)SS * SS * 2 + (long)S4 * SS + (long)SS * KFC
                         + (long)BB * KFC + (long)TT * BB;
        pack_all<<<(unsigned)((total + 255) / 256), 256>>>(
            fc1W, fc2W, WW, fcW, state, acts, latent, rb, rewards,
            fc1e, fc2b, WWb, fcWb, hsb);
    }

    dim3 gS(SS / 64, BB / 64, 2);   // (32, 4, 2) = 256 CTAs, split-K2
    dim3 gB(S4 / 128, BB / 128);    // (64, 2) = 128 CTAs

    int epoch = 1;

    // hidden = cell = relu(fc(hs0)): one GEMM, dual store
    gemm3<64,64,32,32,128,2,3,1><<<gS, 128, SMEM_S>>>(
        hsb, fcWb, fcb, hb, cell, SS, KFC,
        nullptr, nullptr, nullptr, nullptr, nullptr, nullptr, nullptr, 0, epoch++);

    for (int t = 0; t < TT; ++t) {
        gemm3<64,64,32,32,128,2,1,1><<<gS, 128, SMEM_S>>>(
            hb,  fc1e, nullptr, x1b, nullptr, SS, SS,
            nullptr, nullptr, nullptr, nullptr, nullptr, nullptr, nullptr, 0, epoch++);
        gemm3<64,64,32,32,128,2,1,1><<<gS, 128, SMEM_S>>>(
            x1b, fc2b, nullptr, x2b, nullptr, SS, SS,
            nullptr, nullptr, nullptr, nullptr, nullptr, nullptr, nullptr, 0, epoch++);
        // G3 + fused LSTM gates / reward / hs update
        gemm3<128,128,64,32,256,2,4,0><<<gB, 256, SMEM_B>>>(
            x2b, WWb, nullptr, nullptr, nullptr, S4, SS,
            cell, rW, rewards, acts, latent, preds, hsb, t, 0);
        if (t + 1 < TT)
            gemm3<64,64,32,32,128,2,2,1><<<gS, 128, SMEM_S>>>(
                hsb, fcWb, fcb, hb, nullptr, SS, KFC,
                nullptr, nullptr, nullptr, nullptr, nullptr, nullptr, nullptr, 0, epoch++);
    }
}

// round 12
// speedup vs baseline: 1.1173x; 1.0337x over previous
#include <cuda_runtime.h>
#include <cuda_bf16.h>
#include <mma.h>

using namespace nvcuda;

// Problem constants
#define BB   256
#define TT   32
#define SS   2048
#define AA   64
#define PP   128
#define KFC  (SS + AA + PP)   // 2240
#define KAL  (AA + PP)        // 192
#define S4   (4 * SS)         // 8192

#define BKT  64
#define LDT  (BKT + 8)        // 72 bf16 smem stride

// ---------------------------------------------------------------------------
// Scratch (static device globals; no allocation anywhere)
// ---------------------------------------------------------------------------
__device__ __nv_bfloat16 g_fc1e [(long)SS * 2 * SS];     // fc1_eff packed [hi|lo]
__device__ __nv_bfloat16 g_fc2b [(long)SS * 2 * SS];
__device__ __nv_bfloat16 g_WWb  [(long)S4 * 2 * SS];
__device__ __nv_bfloat16 g_fcWh [(long)SS * 2 * SS];     // fc_W[:, :S] packed
__device__ __nv_bfloat16 g_fcWal[(long)SS * 2 * KAL];    // fc_W[:, S:] packed
__device__ __nv_bfloat16 g_alb  [(long)TT * BB * 2 * KAL]; // cat[act_t, latent] packed
__device__ float         g_add  [(long)TT * BB * SS];    // act/latent fc term (+fc_b)
__device__ __nv_bfloat16 g_hb   [(long)BB * 2 * SS];     // carry h (fc out), packed
__device__ __nv_bfloat16 g_hnext[(long)BB * 2 * SS];     // gates out (fc in), packed
__device__ __nv_bfloat16 g_x1b  [(long)BB * 2 * SS];
__device__ __nv_bfloat16 g_x2b  [(long)BB * 2 * SS];
__device__ float         g_cc   [(long)BB * S4];
__device__ float         g_cell [(long)BB * SS];
__device__ float         g_part [(long)BB * SS];         // split-K fp32 partials
__device__ int           g_flags[256];                   // split-K epoch flags (0-init)

// ---------------------------------------------------------------------------
// Helpers
// ---------------------------------------------------------------------------
__device__ __forceinline__ void split_write(__nv_bfloat16* hi_p, __nv_bfloat16* lo_p, float v) {
    __nv_bfloat16 h = __float2bfloat16(v);
    *hi_p = h;
    *lo_p = __float2bfloat16(v - __bfloat162float(h));
}
__device__ __forceinline__ int ld_acq(const int* p) {
    int v;
    asm volatile("ld.acquire.gpu.global.b32 %0, [%1];" : "=r"(v) : "l"(p) : "memory");
    return v;
}
__device__ __forceinline__ void st_rel(int* p, int v) {
    asm volatile("st.release.gpu.global.b32 [%0], %1;" :: "l"(p), "r"(v) : "memory");
}

// One merged pack/init kernel.
__global__ void pack_all(const float* __restrict__ fc1W, const float* __restrict__ fc2W,
                         const float* __restrict__ WW,   const float* __restrict__ fcW,
                         const float* __restrict__ state, const float* __restrict__ acts,
                         const float* __restrict__ latent,
                         __nv_bfloat16* __restrict__ fc1e, __nv_bfloat16* __restrict__ fc2b,
                         __nv_bfloat16* __restrict__ WWb,  __nv_bfloat16* __restrict__ fcWh,
                         __nv_bfloat16* __restrict__ fcWal, __nv_bfloat16* __restrict__ alb,
                         __nv_bfloat16* __restrict__ hnext)
{
    const long N1 = (long)SS * SS;
    const long N2 = N1 + (long)SS * SS;
    const long N3 = N2 + (long)S4 * SS;
    const long N4 = N3 + (long)SS * SS;
    const long N5 = N4 + (long)SS * KAL;
    const long N6 = N5 + (long)TT * BB * KAL;
    const long N7 = N6 + (long)BB * SS;
    long idx = (long)blockIdx.x * 256 + threadIdx.x;
    if (idx < N1) {
        long n = idx / SS, k = idx % SS;
        float v = fc1W[n * 2 * SS + k] + fc1W[n * 2 * SS + SS + k];
        split_write(&fc1e[n * 2 * SS + k], &fc1e[n * 2 * SS + SS + k], v);
    } else if (idx < N2) {
        long j = idx - N1;
        long n = j / SS, k = j % SS;
        split_write(&fc2b[n * 2 * SS + k], &fc2b[n * 2 * SS + SS + k], fc2W[j]);
    } else if (idx < N3) {
        long j = idx - N2;
        long n = j / SS, k = j % SS;
        split_write(&WWb[n * 2 * SS + k], &WWb[n * 2 * SS + SS + k], WW[j]);
    } else if (idx < N4) {
        long j = idx - N3;
        long n = j / SS, k = j % SS;
        split_write(&fcWh[n * 2 * SS + k], &fcWh[n * 2 * SS + SS + k], fcW[n * KFC + k]);
    } else if (idx < N5) {
        long j = idx - N4;
        long n = j / KAL, k = j % KAL;
        split_write(&fcWal[n * 2 * KAL + k], &fcWal[n * 2 * KAL + KAL + k],
                    fcW[n * KFC + SS + k]);
    } else if (idx < N6) {
        long j = idx - N5;
        long r = j / KAL;            // r = t*BB + b
        int  k = (int)(j % KAL);
        int  t = (int)(r / BB), b = (int)(r % BB);
        float v = (k < AA) ? acts[(long)b * (TT * AA) + t * AA + k]
                           : latent[(long)b * PP + (k - AA)];
        split_write(&alb[r * 2 * KAL + k], &alb[r * 2 * KAL + KAL + k], v);
    } else if (idx < N7) {
        long j = idx - N6;
        long b = j / SS, k = j % SS;
        split_write(&hnext[b * 2 * SS + k], &hnext[b * 2 * SS + SS + k],
                    state[b * SS + k]);
    }
}

// ---------------------------------------------------------------------------
// Split-bf16 GEMM (Ozaki 3-term):  C[M, N] = A[M,K] @ W[N,K]^T
// A, W packed [.,2K] bf16 [hi|lo]; per 64-K chunk: Ah*Wh + Ah*Wl + Al*Wh.
// EPI: 0 relu + fp32 store                     (G3 -> cc)
//      1 relu + split-bf16 store               (G1, G2)
//      5 col-bias + fp32 store, NO relu        (add_term precompute)
//      6 row-bias + relu + split-bf16 store    (fc steps; bias = g_add + t*BB*SS)
//      7 = 6 + fp32 dual store                 (init: h and cell)
// SPLITK=1: grid.z=2; z=1 publishes fp32 partial + epoch flag; z=0 combines.
// ---------------------------------------------------------------------------
#define CP16(s, g) asm volatile("cp.async.cg.shared.global [%0], [%1], 16;\n" :: "r"(s), "l"(g))

template<int BMp, int BNp, int WM, int WN, int THREADS, int STAGES, int EPI, int SPLITK>
__global__ __launch_bounds__(THREADS, 1)
void gemm3(const __nv_bfloat16* __restrict__ Ab,
           const __nv_bfloat16* __restrict__ Wb,
           const float* __restrict__ bias,
           void* __restrict__ Cout,
           float* __restrict__ Cdual,
           int N, int K, int epoch)
{
    extern __shared__ __align__(16) __nv_bfloat16 smem[];
    constexpr int TA = BMp * LDT;
    constexpr int TW = BNp * LDT;
    constexpr int STG = 2 * TA + 2 * TW;   // elements per stage

    const int tid = threadIdx.x;
    const int m0 = blockIdx.y * BMp;
    const int n0 = blockIdx.x * BNp;
    const int lda = 2 * K;

    const int ctot = K / BKT;
    int cbeg = 0, cend = ctot;
    if constexpr (SPLITK) {
        const int c0 = (ctot + 1) / 2;
        if (blockIdx.z == 0) cend = c0; else cbeg = c0;
    }
    const int nch = cend - cbeg;

    auto load_stage = [&](int buf, int c) {
        const int kb = c * BKT;
        __nv_bfloat16* sAhi = smem + buf * STG;
        __nv_bfloat16* sAlo = sAhi + TA;
        __nv_bfloat16* sWhi = sAlo + TA;
        __nv_bfloat16* sWlo = sWhi + TW;
#pragma unroll
        for (int i = 0; i < BMp * 8 / THREADS; ++i) {
            int f = tid + i * THREADS;
            int r = f >> 3, cb = (f & 7) * 8;
            const __nv_bfloat16* g = Ab + (long)(m0 + r) * lda + kb + cb;
            CP16((unsigned)__cvta_generic_to_shared(sAhi + r * LDT + cb), g);
            CP16((unsigned)__cvta_generic_to_shared(sAlo + r * LDT + cb), g + K);
        }
#pragma unroll
        for (int i = 0; i < BNp * 8 / THREADS; ++i) {
            int f = tid + i * THREADS;
            int r = f >> 3, cb = (f & 7) * 8;
            const __nv_bfloat16* g = Wb + (long)(n0 + r) * lda + kb + cb;
            CP16((unsigned)__cvta_generic_to_shared(sWhi + r * LDT + cb), g);
            CP16((unsigned)__cvta_generic_to_shared(sWlo + r * LDT + cb), g + K);
        }
        asm volatile("cp.async.commit_group;\n");
    };

    constexpr int WGX = BNp / WN;
    constexpr int MI = WM / 16, NI = WN / 16;
    const int w = tid >> 5;
    const int wy = w / WGX, wx = w % WGX;

    wmma::fragment<wmma::accumulator, 16, 16, 16, float> acc[MI][NI];
#pragma unroll
    for (int i = 0; i < MI; ++i)
#pragma unroll
        for (int j = 0; j < NI; ++j) wmma::fill_fragment(acc[i][j], 0.0f);

#pragma unroll
    for (int s = 0; s < STAGES - 1; ++s)
        if (s < nch) load_stage(s % STAGES, cbeg + s);

    for (int r = 0; r < nch; ++r) {
        const int cur = r % STAGES;
        if (r + STAGES - 1 < nch) {
            load_stage((r + STAGES - 1) % STAGES, cbeg + r + STAGES - 1);
            asm volatile("cp.async.wait_group %0;\n" :: "n"(STAGES - 1));
        } else {
            asm volatile("cp.async.wait_group 0;\n");
        }
        __syncthreads();

        const __nv_bfloat16* sAhi = smem + cur * STG;
        const __nv_bfloat16* sAlo = sAhi + TA;
        const __nv_bfloat16* sWhi = sAlo + TA;
        const __nv_bfloat16* sWlo = sWhi + TW;

#pragma unroll
        for (int ks = 0; ks < BKT / 16; ++ks) {
            wmma::fragment<wmma::matrix_a, 16, 16, 16, __nv_bfloat16, wmma::row_major> ah[MI], al[MI];
            wmma::fragment<wmma::matrix_b, 16, 16, 16, __nv_bfloat16, wmma::col_major> bh[NI], bl[NI];
#pragma unroll
            for (int i = 0; i < MI; ++i) {
                wmma::load_matrix_sync(ah[i], sAhi + (wy * WM + 16 * i) * LDT + ks * 16, LDT);
                wmma::load_matrix_sync(al[i], sAlo + (wy * WM + 16 * i) * LDT + ks * 16, LDT);
            }
#pragma unroll
            for (int j = 0; j < NI; ++j) {
                wmma::load_matrix_sync(bh[j], sWhi + (wx * WN + 16 * j) * LDT + ks * 16, LDT);
                wmma::load_matrix_sync(bl[j], sWlo + (wx * WN + 16 * j) * LDT + ks * 16, LDT);
            }
#pragma unroll
            for (int i = 0; i < MI; ++i)
#pragma unroll
                for (int j = 0; j < NI; ++j) {
                    wmma::mma_sync(acc[i][j], ah[i], bh[j], acc[i][j]);
                    wmma::mma_sync(acc[i][j], ah[i], bl[j], acc[i][j]);
                    wmma::mma_sync(acc[i][j], al[i], bh[j], acc[i][j]);
                }
        }
        __syncthreads();
    }

    // Stage accumulators in smem.
    constexpr int LDCc = BNp + 4;
    float* stage = reinterpret_cast<float*>(smem);
#pragma unroll
    for (int i = 0; i < MI; ++i)
#pragma unroll
        for (int j = 0; j < NI; ++j)
            wmma::store_matrix_sync(stage + (wy * WM + 16 * i) * LDCc + wx * WN + 16 * j,
                                    acc[i][j], LDCc, wmma::mem_row_major);
    __syncthreads();

    int* flagp = nullptr;
    if constexpr (SPLITK) {
        flagp = &g_flags[blockIdx.y * gridDim.x + blockIdx.x];
        if (blockIdx.z == 1) {
#pragma unroll
            for (int i = 0; i < BMp * BNp / 4 / THREADS; ++i) {
                int f = tid + i * THREADS;
                int row = f / (BNp / 4);
                int c4  = (f % (BNp / 4)) * 4;
                float4 v4 = *reinterpret_cast<float4*>(&stage[row * LDCc + c4]);
                *reinterpret_cast<float4*>(&g_part[(long)(m0 + row) * N + n0 + c4]) = v4;
            }
            __threadfence();
            __syncthreads();
            if (tid == 0) st_rel(flagp, epoch);
            return;
        }
        if (tid == 0) {
            while (ld_acq(flagp) != epoch) __nanosleep(32);
        }
        __syncthreads();
    }

#pragma unroll
    for (int i = 0; i < BMp * BNp / 4 / THREADS; ++i) {
        int f = tid + i * THREADS;
        int row = f / (BNp / 4);
        int c4  = (f % (BNp / 4)) * 4;
        float4 v4 = *reinterpret_cast<float4*>(&stage[row * LDCc + c4]);
        float v[4] = {v4.x, v4.y, v4.z, v4.w};
        long gm = m0 + row;

        if constexpr (SPLITK) {
            float4 p4 = *reinterpret_cast<const float4*>(&g_part[gm * (long)N + n0 + c4]);
            v[0] += p4.x; v[1] += p4.y; v[2] += p4.z; v[3] += p4.w;
        }

        if constexpr (EPI == 5) {
            // add_term precompute: col bias (fc_b), NO relu, fp32 store
#pragma unroll
            for (int q = 0; q < 4; ++q) v[q] += bias[n0 + c4 + q];
            *reinterpret_cast<float4*>((float*)Cout + gm * (long)N + n0 + c4) =
                make_float4(v[0], v[1], v[2], v[3]);
        } else if constexpr (EPI == 0) {
#pragma unroll
            for (int q = 0; q < 4; ++q) v[q] = fmaxf(v[q], 0.0f);
            *reinterpret_cast<float4*>((float*)Cout + gm * (long)N + n0 + c4) =
                make_float4(v[0], v[1], v[2], v[3]);
        } else {
            if constexpr (EPI == 6 || EPI == 7) {
                const float* rb4 = bias + gm * (long)N + n0 + c4;
#pragma unroll
                for (int q = 0; q < 4; ++q) v[q] += rb4[q];
            }
#pragma unroll
            for (int q = 0; q < 4; ++q) v[q] = fmaxf(v[q], 0.0f);
            __nv_bfloat16* cp = (__nv_bfloat16*)Cout + gm * (2L * N);
            __nv_bfloat16 h[4]; float lo[4];
#pragma unroll
            for (int q = 0; q < 4; ++q) {
                h[q]  = __float2bfloat16(v[q]);
                lo[q] = v[q] - __bfloat162float(h[q]);
            }
            __nv_bfloat162 hh0; hh0.x = h[0]; hh0.y = h[1];
            __nv_bfloat162 hh1; hh1.x = h[2]; hh1.y = h[3];
            reinterpret_cast<__nv_bfloat162*>(cp + n0 + c4)[0] = hh0;
            reinterpret_cast<__nv_bfloat162*>(cp + n0 + c4)[1] = hh1;
            __nv_bfloat162 ll0; ll0.x = __float2bfloat16(lo[0]); ll0.y = __float2bfloat16(lo[1]);
            __nv_bfloat162 ll1; ll1.x = __float2bfloat16(lo[2]); ll1.y = __float2bfloat16(lo[3]);
            reinterpret_cast<__nv_bfloat162*>(cp + N + n0 + c4)[0] = ll0;
            reinterpret_cast<__nv_bfloat162*>(cp + N + n0 + c4)[1] = ll1;
            if constexpr (EPI == 7) {
                *reinterpret_cast<float4*>(Cdual + gm * (long)N + n0 + c4) =
                    make_float4(v[0], v[1], v[2], v[3]);
            }
        }
    }

    if constexpr (SPLITK) {
        if (tid == 0) *flagp = 0;   // reset for next epoch (ordered by kernel boundary)
    }
}

// ---------------------------------------------------------------------------
// LSTM gates + reward + h_next split store. One block per batch row.
// ---------------------------------------------------------------------------
__global__ __launch_bounds__(256)
void gates_kernel(const float* __restrict__ cc, float* __restrict__ cell,
                  const float* __restrict__ rW, const float* __restrict__ rb,
                  int t, float* __restrict__ preds, float* __restrict__ rewards,
                  __nv_bfloat16* __restrict__ hnext)
{
    const int b = blockIdx.x, tid = threadIdx.x;
    const float* ccb = cc + (long)b * S4;
    float* cb  = cell + (long)b * SS;
    float* pr  = preds + ((long)t * BB + b) * SS;
    __nv_bfloat16* hn = hnext + (long)b * (2 * SS);

    float rsum = 0.f;
#pragma unroll
    for (int i = 0; i < 8; ++i) {
        int s = tid + i * 256;
        float ci = ccb[s];
        float cf = ccb[SS + s];
        float co = ccb[2 * SS + s];
        float cg = ccb[3 * SS + s];
        float ig = 1.f / (1.f + expf(-ci));
        float fg = 1.f / (1.f + expf(-cf));
        float og = 1.f / (1.f + expf(-co));
        float gg = tanhf(cg);
        float cn = fg * cb[s] + ig * gg;
        cb[s] = cn;
        float h = og * tanhf(cn);
        pr[s] = h;
        split_write(&hn[s], &hn[SS + s], h);
        rsum += h * rW[s];
    }

    __shared__ float red[256];
    red[tid] = rsum;
    __syncthreads();
    for (int s2 = 128; s2 > 0; s2 >>= 1) {
        if (tid < s2) red[tid] += red[tid + s2];
        __syncthreads();
    }
    if (tid == 0) rewards[(long)t * BB + b] = red[0] + rb[0];
}

// ---------------------------------------------------------------------------
// Launch
// ---------------------------------------------------------------------------
// Small config: 64x64 tile, 4 warps (32x32), 3 stages, split-K2 -> 2 CTA/SM.
#define SMEM_S (3 * (4 * 64 * LDT) * (int)sizeof(__nv_bfloat16))    // 110592 B
// Big config: 128x128 tile, 8 warps (64x32), 2 stages.
#define SMEM_B (2 * (4 * 128 * LDT) * (int)sizeof(__nv_bfloat16))   // 147456 B

extern "C" void kernel_launch(void* const* d_in, const int* /*in_sizes*/, int /*n_in*/,
                              void* d_out, int /*out_size*/) {
    const float* state  = (const float*)d_in[0];
    const float* acts   = (const float*)d_in[1];
    const float* latent = (const float*)d_in[2];
    const float* fcW    = (const float*)d_in[3];
    const float* fcb    = (const float*)d_in[4];
    const float* fc1W   = (const float*)d_in[5];
    const float* fc2W   = (const float*)d_in[6];
    const float* WW     = (const float*)d_in[7];
    const float* rW     = (const float*)d_in[8];
    const float* rb     = (const float*)d_in[9];

    float* preds   = (float*)d_out;
    float* rewards = preds + (long)TT * BB * SS;

    __nv_bfloat16 *fc1e, *fc2b, *WWb, *fcWh, *fcWal, *alb, *hb, *hnext, *x1b, *x2b;
    float *cc, *cell, *addt;
    cudaGetSymbolAddress((void**)&fc1e,  g_fc1e);
    cudaGetSymbolAddress((void**)&fc2b,  g_fc2b);
    cudaGetSymbolAddress((void**)&WWb,   g_WWb);
    cudaGetSymbolAddress((void**)&fcWh,  g_fcWh);
    cudaGetSymbolAddress((void**)&fcWal, g_fcWal);
    cudaGetSymbolAddress((void**)&alb,   g_alb);
    cudaGetSymbolAddress((void**)&addt,  g_add);
    cudaGetSymbolAddress((void**)&hb,    g_hb);
    cudaGetSymbolAddress((void**)&hnext, g_hnext);
    cudaGetSymbolAddress((void**)&x1b,   g_x1b);
    cudaGetSymbolAddress((void**)&x2b,   g_x2b);
    cudaGetSymbolAddress((void**)&cc,    g_cc);
    cudaGetSymbolAddress((void**)&cell,  g_cell);

    cudaFuncSetAttribute((const void*)gemm3<64,64,32,32,128,3,1,1>,   cudaFuncAttributeMaxDynamicSharedMemorySize, SMEM_S);
    cudaFuncSetAttribute((const void*)gemm3<64,64,32,32,128,3,6,1>,   cudaFuncAttributeMaxDynamicSharedMemorySize, SMEM_S);
    cudaFuncSetAttribute((const void*)gemm3<64,64,32,32,128,3,7,1>,   cudaFuncAttributeMaxDynamicSharedMemorySize, SMEM_S);
    cudaFuncSetAttribute((const void*)gemm3<128,128,64,32,256,2,0,0>, cudaFuncAttributeMaxDynamicSharedMemorySize, SMEM_B);
    cudaFuncSetAttribute((const void*)gemm3<128,128,64,32,256,2,5,0>, cudaFuncAttributeMaxDynamicSharedMemorySize, SMEM_B);

    // One merged pack/init launch.
    {
        const long total = (long)SS * SS * 3 + (long)S4 * SS + (long)SS * KAL
                         + (long)TT * BB * KAL + (long)BB * SS;
        pack_all<<<(unsigned)((total + 255) / 256), 256>>>(
            fc1W, fc2W, WW, fcW, state, acts, latent,
            fc1e, fc2b, WWb, fcWh, fcWal, alb, hnext);
    }

    // Precompute add_term[t,b,:] = [act_t, latent] @ fcW[:,S:]^T + fc_b
    {
        dim3 gP(SS / 128, (TT * BB) / 128);   // (16, 64)
        gemm3<128,128,64,32,256,2,5,0><<<gP, 256, SMEM_B>>>(
            alb, fcWal, fcb, addt, nullptr, SS, KAL, 0);
    }

    dim3 gS(SS / 64, BB / 64, 2);   // (32, 4, 2) = 256 CTAs, split-K2
    dim3 gB(S4 / 128, BB / 128);    // (64, 2) = 128 CTAs

    int epoch = 1;

    // hidden = cell = relu(state @ fcWh^T + add_term[0]): dual store
    gemm3<64,64,32,32,128,3,7,1><<<gS, 128, SMEM_S>>>(
        hnext, fcWh, addt, hb, cell, SS, SS, epoch++);

    for (int t = 0; t < TT; ++t) {
        gemm3<64,64,32,32,128,3,1,1><<<gS, 128, SMEM_S>>>(
            hb,  fc1e, nullptr, x1b, nullptr, SS, SS, epoch++);
        gemm3<64,64,32,32,128,3,1,1><<<gS, 128, SMEM_S>>>(
            x1b, fc2b, nullptr, x2b, nullptr, SS, SS, epoch++);
        gemm3<128,128,64,32,256,2,0,0><<<gB, 256, SMEM_B>>>(
            x2b, WWb, nullptr, cc, nullptr, S4, SS, 0);
        gates_kernel<<<BB, 256>>>(cc, cell, rW, rb, t, preds, rewards, hnext);
        if (t + 1 < TT)
            gemm3<64,64,32,32,128,3,6,1><<<gS, 128, SMEM_S>>>(
                hnext, fcWh, addt + (long)t * BB * SS, hb, nullptr, SS, SS, epoch++);
    }
}